// round 6
// baseline (speedup 1.0000x reference)
#include <cuda_runtime.h>
#include <cuda_bf16.h>

// TuckerFacLayer — constant-memory Wo + L2-prefetched FFMA2 version.
//   x:          (B=2, V=8, T=4, N=1024, D=16, F_IN=64)  float32
//   var_idx:    (B, V)                                   int32
//   core:       (RV=4, R=16, R=16)                       float32
//   factor_vars:(NVAR=8, RV=4)                           float32
//   fac_in:     (R=16, F_IN=64)                          float32
//   fac_out:    (R=16, F_OUT=64)                         float32
//   out:        (B, V, T, N, D, F_OUT=64)                float32
//
// Per row r in bv-chunk:
//   y1[B]  = sum_a x[a]*fac_in[B][a]
//   out[e] = sum_B y1[B]*Wo[bv][B][e]
// where Wo[bv][B][e] = sum_C (sum_A fv[bv][A]*core[A][B][C]) * fac_out[C][e].

typedef unsigned long long u64;

__device__ __forceinline__ u64 pack2(float lo, float hi) {
    u64 r;
    asm("mov.b64 %0, {%1, %2};" : "=l"(r) : "f"(lo), "f"(hi));
    return r;
}
__device__ __forceinline__ void unpack2(u64 v, float& lo, float& hi) {
    asm("mov.b64 {%0, %1}, %2;" : "=f"(lo), "=f"(hi) : "l"(v));
}
// Packed fp32x2 FMA: d = a*b + c on two fp32 lanes.
__device__ __forceinline__ u64 ffma2(u64 a, u64 b, u64 c) {
    u64 d;
    asm("fma.rn.f32x2 %0, %1, %2, %3;" : "=l"(d) : "l"(a), "l"(b), "l"(c));
    return d;
}
__device__ __forceinline__ void prefetch_l2(const void* p) {
    asm volatile("prefetch.global.L2 [%0];" :: "l"(p));
}

static constexpr int RV_   = 4;
static constexpr int R_    = 16;
static constexpr int FIN_  = 64;
static constexpr int FOUT_ = 64;
static constexpr int NBV_  = 16;                         // B*V
static constexpr int THREADS = 128;
static constexpr int ROWS    = 4;                        // rows per thread
static constexpr int ROWS_PER_BLOCK = THREADS * ROWS;    // 512
static constexpr long long TOTAL_ROWS = 2LL * 8 * 4 * 1024 * 16;  // 1048576
static constexpr int PF = 6;                             // L2 prefetch distance (q-steps)

// All 16 per-bv Wo matrices: [bv][B][e] as float4 chunks -> 16*16*16 float4 = 64 KB
__constant__ float4 c_Wo4[NBV_ * R_ * (FOUT_ / 4)];
__device__   float  g_Wo [NBV_ * R_ * FOUT_];            // scratch, same layout as floats

// ---------------------------------------------------------------------------
// Kernel 1: compute Wo for every bv into g_Wo. grid = 16 blocks x 64 threads.
// ---------------------------------------------------------------------------
__global__ void wo_precompute_kernel(const int*   __restrict__ var_idx,
                                     const float* __restrict__ core,
                                     const float* __restrict__ factor_vars,
                                     const float* __restrict__ fac_out)
{
    const int bv = blockIdx.x;
    const int t  = threadIdx.x;             // 0..63
    const int vi = var_idx[bv];

    __shared__ float sW[R_ * R_];           // W[B][C]
    const float fv0 = factor_vars[vi * RV_ + 0];
    const float fv1 = factor_vars[vi * RV_ + 1];
    const float fv2 = factor_vars[vi * RV_ + 2];
    const float fv3 = factor_vars[vi * RV_ + 3];

    #pragma unroll
    for (int k = 0; k < 4; ++k) {           // 256 entries / 64 threads
        const int i = t + k * 64;
        sW[i] = fv0 * core[0 * 256 + i]
              + fv1 * core[1 * 256 + i]
              + fv2 * core[2 * 256 + i]
              + fv3 * core[3 * 256 + i];
    }
    __syncthreads();

    const int e = t;                        // one output column per thread
    #pragma unroll
    for (int B = 0; B < R_; ++B) {
        float acc = 0.0f;
        #pragma unroll
        for (int C = 0; C < R_; ++C)
            acc += sW[B * R_ + C] * fac_out[C * FOUT_ + e];
        g_Wo[bv * (R_ * FOUT_) + B * FOUT_ + e] = acc;
    }
}

// ---------------------------------------------------------------------------
// Kernel 2: main per-row compute. 4 rows/thread; fin from SMEM, Wo from LDC.
// ---------------------------------------------------------------------------
__global__ void __launch_bounds__(THREADS, 4)
tucker_fac_kernel(const float* __restrict__ x,
                  const float* __restrict__ fac_in,
                  float* __restrict__ out)
{
    __shared__ __align__(16) float s_fin[FIN_][R_];   // [a][B] = fac_in[B][a]

    const int tid = threadIdx.x;
    const long long row_base = (long long)blockIdx.x * ROWS_PER_BLOCK;
    const int bv = (int)(row_base >> 16);   // 65536 rows per (b,v); 512 | 65536
    const int wo_base = bv * (R_ * (FOUT_ / 4));   // float4 index base into c_Wo4

    // fin transpose into SMEM
    #pragma unroll
    for (int k = 0; k < 8; ++k) {           // 1024 entries / 128 threads
        const int i = tid + k * THREADS;
        const int a = i >> 4, Bq = i & 15;
        s_fin[a][Bq] = fac_in[Bq * FIN_ + a];
    }
    __syncthreads();

    const long long r0 = row_base + tid;    // rows r0 + j*THREADS, j=0..3
    const float4* xp[ROWS];
    #pragma unroll
    for (int r = 0; r < ROWS; ++r)
        xp[r] = reinterpret_cast<const float4*>(x + (r0 + r * THREADS) * 64);

    // ---------------- Phase 1: y1[r][B] = sum_a x[r][a] * s_fin[a][B] ------
    u64 acc1[ROWS][8];
    #pragma unroll
    for (int r = 0; r < ROWS; ++r)
        #pragma unroll
        for (int j = 0; j < 8; ++j) acc1[r][j] = 0ULL;

    // double-buffer x chunks + L2 prefetch ahead
    float4 cur[ROWS], nxt[ROWS];
    #pragma unroll
    for (int r = 0; r < ROWS; ++r) cur[r] = xp[r][0];
    #pragma unroll
    for (int r = 0; r < ROWS; ++r) prefetch_l2(&xp[r][1 + PF - 1]);

    #pragma unroll
    for (int q = 0; q < 16; ++q) {
        if (q < 15) {
            #pragma unroll
            for (int r = 0; r < ROWS; ++r) nxt[r] = xp[r][q + 1];
            if (q + 1 + PF < 16) {
                #pragma unroll
                for (int r = 0; r < ROWS; ++r) prefetch_l2(&xp[r][q + 1 + PF]);
            }
        }

        #pragma unroll
        for (int c = 0; c < 4; ++c) {
            const int a = q * 4 + c;
            const ulonglong2* wr = reinterpret_cast<const ulonglong2*>(&s_fin[a][0]);
            const ulonglong2 w01 = wr[0], w23 = wr[1], w45 = wr[2], w67 = wr[3];
            #pragma unroll
            for (int r = 0; r < ROWS; ++r) {
                const float v = (c == 0) ? cur[r].x : (c == 1) ? cur[r].y
                              : (c == 2) ? cur[r].z : cur[r].w;
                const u64 xa = pack2(v, v);
                acc1[r][0] = ffma2(xa, w01.x, acc1[r][0]);
                acc1[r][1] = ffma2(xa, w01.y, acc1[r][1]);
                acc1[r][2] = ffma2(xa, w23.x, acc1[r][2]);
                acc1[r][3] = ffma2(xa, w23.y, acc1[r][3]);
                acc1[r][4] = ffma2(xa, w45.x, acc1[r][4]);
                acc1[r][5] = ffma2(xa, w45.y, acc1[r][5]);
                acc1[r][6] = ffma2(xa, w67.x, acc1[r][6]);
                acc1[r][7] = ffma2(xa, w67.y, acc1[r][7]);
            }
        }

        if (q < 15) {
            #pragma unroll
            for (int r = 0; r < ROWS; ++r) cur[r] = nxt[r];
        }
    }

    // Unpack y1 (acc1 registers are renamed, not copied)
    float y[ROWS][16];
    #pragma unroll
    for (int r = 0; r < ROWS; ++r)
        #pragma unroll
        for (int j = 0; j < 8; ++j)
            unpack2(acc1[r][j], y[r][2 * j], y[r][2 * j + 1]);

    // ---------------- Phase 2: out[r][e] = sum_B y[r][B] * Wo[B][e] --------
    // Two half-passes of 2 rows each keep acc2 at 32 regs; weights via LDC
    // (constant port) so the repeat costs no L1 wavefronts.
    float4* op[ROWS];
    #pragma unroll
    for (int r = 0; r < ROWS; ++r)
        op[r] = reinterpret_cast<float4*>(out + (r0 + r * THREADS) * 64);

    #pragma unroll
    for (int half = 0; half < 2; ++half) {
        const int rA = 2 * half, rB = 2 * half + 1;

        #pragma unroll
        for (int ec = 0; ec < 4; ++ec) {
            u64 accA[8], accB[8];
            #pragma unroll
            for (int j = 0; j < 8; ++j) { accA[j] = 0ULL; accB[j] = 0ULL; }

            #pragma unroll
            for (int Bq = 0; Bq < 16; ++Bq) {
                // 4 x LDC.128 (uniform broadcast on the constant port)
                union { float4 f; ulonglong2 u; } w0c, w1c, w2c, w3c;
                const int wi = wo_base + Bq * 16 + ec * 4;
                w0c.f = c_Wo4[wi + 0];
                w1c.f = c_Wo4[wi + 1];
                w2c.f = c_Wo4[wi + 2];
                w3c.f = c_Wo4[wi + 3];

                const u64 ya = pack2(y[rA][Bq], y[rA][Bq]);
                const u64 yb = pack2(y[rB][Bq], y[rB][Bq]);

                accA[0] = ffma2(ya, w0c.u.x, accA[0]);
                accA[1] = ffma2(ya, w0c.u.y, accA[1]);
                accA[2] = ffma2(ya, w1c.u.x, accA[2]);
                accA[3] = ffma2(ya, w1c.u.y, accA[3]);
                accA[4] = ffma2(ya, w2c.u.x, accA[4]);
                accA[5] = ffma2(ya, w2c.u.y, accA[5]);
                accA[6] = ffma2(ya, w3c.u.x, accA[6]);
                accA[7] = ffma2(ya, w3c.u.y, accA[7]);

                accB[0] = ffma2(yb, w0c.u.x, accB[0]);
                accB[1] = ffma2(yb, w0c.u.y, accB[1]);
                accB[2] = ffma2(yb, w1c.u.x, accB[2]);
                accB[3] = ffma2(yb, w1c.u.y, accB[3]);
                accB[4] = ffma2(yb, w2c.u.x, accB[4]);
                accB[5] = ffma2(yb, w2c.u.y, accB[5]);
                accB[6] = ffma2(yb, w3c.u.x, accB[6]);
                accB[7] = ffma2(yb, w3c.u.y, accB[7]);
            }

            #pragma unroll
            for (int h = 0; h < 4; ++h) {
                union { u64 u[2]; float4 f; } cvA, cvB;
                cvA.u[0] = accA[2 * h]; cvA.u[1] = accA[2 * h + 1];
                cvB.u[0] = accB[2 * h]; cvB.u[1] = accB[2 * h + 1];
                op[rA][ec * 4 + h] = cvA.f;        // STG.128
                op[rB][ec * 4 + h] = cvB.f;
            }
        }
    }
}

extern "C" void kernel_launch(void* const* d_in, const int* in_sizes, int n_in,
                              void* d_out, int out_size)
{
    const float* x           = (const float*)d_in[0];
    const int*   var_idx     = (const int*)  d_in[1];
    const float* core        = (const float*)d_in[2];
    const float* factor_vars = (const float*)d_in[3];
    const float* fac_in      = (const float*)d_in[4];
    const float* fac_out     = (const float*)d_in[5];
    float* out = (float*)d_out;

    // 1) Compute all per-bv Wo matrices into device scratch.
    wo_precompute_kernel<<<NBV_, 64>>>(var_idx, core, factor_vars, fac_out);

    // 2) Move them into __constant__ (async D2D memcpy — graph-capturable).
    void* g_wo_ptr = nullptr;
    cudaGetSymbolAddress(&g_wo_ptr, g_Wo);
    cudaMemcpyToSymbolAsync(c_Wo4, g_wo_ptr,
                            NBV_ * R_ * FOUT_ * sizeof(float), 0,
                            cudaMemcpyDeviceToDevice, 0);

    // 3) Main per-row kernel.
    const int grid = (int)(TOTAL_ROWS / ROWS_PER_BLOCK);  // 2048
    tucker_fac_kernel<<<grid, THREADS>>>(x, fac_in, out);
}